// round 2
// baseline (speedup 1.0000x reference)
#include <cuda_runtime.h>
#include <cstddef>

#define CDIM   256
#define KCODES 1024
#define HW     1024          // 32*32
#define NIMG   32
#define NVEC   (NIMG * HW)   // 32768
#define QELEMS (NVEC * CDIM) // 8388608

#define TM 64
#define TN 128
#define TK 32

__device__ float  g_ne[KCODES];   // full ||e_k||^2 (fp32), matching reference's B term
__device__ double g_loss;

// -------- prep: squared norms of codebook rows + zero loss accumulator
__global__ void vq_prep(const float* __restrict__ E) {
    int code = blockIdx.x;
    if (code == 0 && threadIdx.x == 0) g_loss = 0.0;
    const float* row = E + (size_t)code * CDIM;
    float s = 0.f;
    for (int c = threadIdx.x; c < CDIM; c += 128) {
        float v = row[c];
        s += v * v;
    }
    __shared__ float red[4];
    for (int o = 16; o > 0; o >>= 1) s += __shfl_down_sync(0xffffffffu, s, o);
    if ((threadIdx.x & 31) == 0) red[threadIdx.x >> 5] = s;
    __syncthreads();
    if (threadIdx.x == 0) g_ne[code] = red[0] + red[1] + red[2] + red[3];
}

// -------- main: fused score-GEMM + quantized-d argmin + gather + loss
__global__ __launch_bounds__(256, 2)
void vq_main(const float* __restrict__ Z, const float* __restrict__ E,
             float* __restrict__ out) {
    __shared__ __align__(16) float As[TM][TK];      // [vec][dim]
    __shared__ __align__(16) float Bsf[TN * TK];    // swizzled [code][dim]
    __shared__ float nes[TN];
    __shared__ int   sidx[TM];
    __shared__ float sred[8];

    const int tid = threadIdx.x;
    const int tx  = tid & 15;   // code direction (8 codes each)
    const int ty  = tid >> 4;   // vector direction (4 vectors each)
    const int v0  = blockIdx.x * TM;
    const int img = v0 >> 10;          // 64 | 1024 -> whole tile in one image
    const int hw0 = v0 & 1023;
    const float* zimg = Z + (size_t)img * (CDIM * HW);

    // per-thread swizzled B offsets (kk XOR-swizzle keyed on code bits)
    int bbase[8], bsw[8];
#pragma unroll
    for (int j = 0; j < 8; j++) {
        int n = tx * 8 + j;
        bbase[j] = n * TK;
        bsw[j]   = ((n ^ (n >> 3)) & 7) << 2;
    }

    float bestd[4];     // running quantized-d minimum (reference semantics)
    int   bidx[4];
    float nz[4];        // fp32 ||z_row||^2, accumulated in a fixed FMA order
#pragma unroll
    for (int i = 0; i < 4; i++) { bestd[i] = 3.4e38f; bidx[i] = 0; nz[i] = 0.f; }

    for (int nt = 0; nt < KCODES / TN; nt++) {
        float acc[4][8];
#pragma unroll
        for (int i = 0; i < 4; i++)
#pragma unroll
            for (int j = 0; j < 8; j++) acc[i][j] = 0.f;

        for (int kt = 0; kt < CDIM / TK; kt++) {
            const int ko = kt * TK;
            __syncthreads();
            if (kt == 0 && tid < TN) nes[tid] = g_ne[nt * TN + tid];
            // A tile: 64 vectors x 32 dims (gmem coalesced along hw)
            {
                int lm  = tid & 63;
                int lc0 = tid >> 6;   // 0..3
#pragma unroll
                for (int jj = 0; jj < 8; jj++) {
                    int cc = lc0 + jj * 4;
                    As[lm][cc] = zimg[(size_t)(ko + cc) * HW + hw0 + lm];
                }
            }
            // B tile: 128 codes x 32 dims, float4 loads, XOR-swizzled store
            {
#pragma unroll
                for (int p = 0; p < 4; p++) {
                    int t   = tid + p * 256;
                    int lc4 = t & 7;
                    int n   = t >> 3;
                    float4 v = *(const float4*)&E[(size_t)(nt * TN + n) * CDIM + ko + lc4 * 4];
                    *(float4*)&Bsf[n * TK + ((lc4 * 4) ^ (((n ^ (n >> 3)) & 7) << 2))] = v;
                }
            }
            __syncthreads();
#pragma unroll
            for (int kq = 0; kq < TK; kq += 4) {
                float4 a[4], b[8];
#pragma unroll
                for (int i = 0; i < 4; i++)
                    a[i] = *(const float4*)&As[ty * 4 + i][kq];
#pragma unroll
                for (int j = 0; j < 8; j++)
                    b[j] = *(const float4*)&Bsf[bbase[j] + (kq ^ bsw[j])];
                if (nt == 0) {
                    // ||z||^2 in a fixed sequential order (identical in all tx lanes)
#pragma unroll
                    for (int i = 0; i < 4; i++) {
                        nz[i] = fmaf(a[i].x, a[i].x, nz[i]);
                        nz[i] = fmaf(a[i].y, a[i].y, nz[i]);
                        nz[i] = fmaf(a[i].z, a[i].z, nz[i]);
                        nz[i] = fmaf(a[i].w, a[i].w, nz[i]);
                    }
                }
#pragma unroll
                for (int i = 0; i < 4; i++)
#pragma unroll
                    for (int j = 0; j < 8; j++) {
                        acc[i][j] = fmaf(a[i].x, b[j].x, acc[i][j]);
                        acc[i][j] = fmaf(a[i].y, b[j].y, acc[i][j]);
                        acc[i][j] = fmaf(a[i].z, b[j].z, acc[i][j]);
                        acc[i][j] = fmaf(a[i].w, b[j].w, acc[i][j]);
                    }
            }
        }
        // fold this code tile with REFERENCE arithmetic:
        //   d = fl( fl(nz - 2*dot) + ne )   (2*dot exact, so fmaf == the ref rounding)
#pragma unroll
        for (int i = 0; i < 4; i++) {
#pragma unroll
            for (int j = 0; j < 8; j++) {
                float t2 = fmaf(-2.0f, acc[i][j], nz[i]);
                float d  = t2 + nes[tx * 8 + j];
                int   n  = nt * TN + tx * 8 + j;
                if (d < bestd[i]) { bestd[i] = d; bidx[i] = n; }  // strict <: first occurrence wins
            }
        }
    }

    // butterfly across the 16 lanes sharing the same vectors (argmin, lowest idx on tie)
#pragma unroll
    for (int i = 0; i < 4; i++) {
        float bd = bestd[i]; int bi = bidx[i];
#pragma unroll
        for (int off = 1; off < 16; off <<= 1) {
            float od = __shfl_xor_sync(0xffffffffu, bd, off);
            int   oi = __shfl_xor_sync(0xffffffffu, bi, off);
            if (od < bd || (od == bd && oi < bi)) { bd = od; bi = oi; }
        }
        if (tx == 0) sidx[ty * 4 + i] = bi;
    }
    __syncthreads();

    // gather codebook rows -> NCHW output, accumulate (z - quant)^2
    float lsum = 0.f;
    {
        int lm  = tid & 63;
        int lc0 = tid >> 6;
        int id  = sidx[lm];
        const float* erow = E + (size_t)id * CDIM;
        float* oimg = out + (size_t)img * (CDIM * HW);
#pragma unroll 8
        for (int p = 0; p < 64; p++) {
            int c = lc0 + p * 4;
            float e  = erow[c];
            float zv = zimg[(size_t)c * HW + hw0 + lm];
            oimg[(size_t)c * HW + hw0 + lm] = e;
            float dd = zv - e;
            lsum += dd * dd;
        }
    }
    for (int o = 16; o > 0; o >>= 1) lsum += __shfl_down_sync(0xffffffffu, lsum, o);
    if ((tid & 31) == 0) sred[tid >> 5] = lsum;
    __syncthreads();
    if (tid == 0) {
        float t = 0.f;
        for (int w = 0; w < 8; w++) t += sred[w];
        atomicAdd(&g_loss, (double)t);
    }
}

// -------- finalize: the two scalar losses (commit = 0.25 * vq, exactly)
__global__ void vq_final(float* out, int out_size) {
    if (out_size >= QELEMS + 1) {
        float vq = (float)(g_loss / (double)QELEMS);
        out[QELEMS] = vq;
        if (out_size >= QELEMS + 2) out[QELEMS + 1] = 0.25f * vq;
    }
}

extern "C" void kernel_launch(void* const* d_in, const int* in_sizes, int n_in,
                              void* d_out, int out_size) {
    const float* Z = (const float*)d_in[0];
    const float* E = (const float*)d_in[1];
    // defensive: identify by size if order ever differs
    if (n_in >= 2 && in_sizes[0] == KCODES * CDIM && in_sizes[1] == QELEMS) {
        const float* t = Z; Z = E; E = t;
    }
    float* out = (float*)d_out;

    vq_prep<<<KCODES, 128>>>(E);
    vq_main<<<NVEC / TM, 256>>>(Z, E, out);
    vq_final<<<1, 1>>>(out, out_size);
}

// round 7
// speedup vs baseline: 2.3562x; 2.3562x over previous
#include <cuda_runtime.h>
#include <cuda_fp16.h>
#include <cuda_pipeline.h>
#include <cstdint>
#include <cstddef>

#define CDIM   256
#define KCODES 1024
#define HW     1024
#define NVEC   32768
#define QELEMS (NVEC * CDIM)

#define ESCALE 2048.0f          // 2^11, exact scaling of E before fp16 split
#define EINV   (1.0f / 2048.0f)

#define FIXCAP  4096
#define FIX_EPS 1.5e-4f         // >= 5 d-grid cells (ulp(d) = 3.05e-5 for d in [256,512))

// ---- dynamic smem layout (bytes) ----
#define SA_H   0                // A-high: 128 rows x 512B (256 fp16), swizzled
#define SA_L   65536            // A-low
#define SB     131072           // 2 buffers x (Bh 16KB + Bl 16KB)
#define SNE    196608           // 1024 floats
#define SBEST  200704           // float[128][2]
#define SSEC   201728           // float[128][2]
#define SIDX   202752           // int[128][2]
#define SROW   203776           // int[128]
#define SRED   204288           // float[8]
#define SMEM_TOTAL 204800

__device__ float  g_ne[KCODES];
__device__ float  g_nz[NVEC];
__device__ double g_loss;
__device__ int    g_fixcnt;
__device__ int    g_fixlist[FIXCAP];
__device__ int    g_code[NVEC];
// E pre-split (scaled by 2^11), [code][k] fp16, 512B rows, XOR-swizzled 16B chunks
__device__ __align__(16) __half g_Bh[KCODES * CDIM];
__device__ __align__(16) __half g_Bl[KCODES * CDIM];

__device__ __forceinline__ uint32_t smem_u32(const void* p) {
    uint32_t a;
    asm("{ .reg .u64 t; cvta.to.shared.u64 t, %1; cvt.u32.u64 %0, t; }" : "=r"(a) : "l"(p));
    return a;
}

#define LDSM4(r, addr) \
    asm volatile("ldmatrix.sync.aligned.m8n8.x4.shared.b16 {%0,%1,%2,%3}, [%4];" \
        : "=r"((r)[0]), "=r"((r)[1]), "=r"((r)[2]), "=r"((r)[3]) : "r"(addr))

#define MMA16816(acc, a, b0, b1) \
    asm volatile("mma.sync.aligned.m16n8k16.row.col.f32.f16.f16.f32 " \
        "{%0,%1,%2,%3}, {%4,%5,%6,%7}, {%8,%9}, {%0,%1,%2,%3};" \
        : "+f"((acc)[0]), "+f"((acc)[1]), "+f"((acc)[2]), "+f"((acc)[3]) \
        : "r"((a)[0]), "r"((a)[1]), "r"((a)[2]), "r"((a)[3]), "r"(b0), "r"(b1))

__device__ __forceinline__ uint32_t pack2(float x0, float x1, float& r0, float& r1) {
    __half h0 = __float2half_rn(x0);
    __half h1 = __float2half_rn(x1);
    r0 = x0 - __half2float(h0);
    r1 = x1 - __half2float(h1);
    return (uint32_t)__half_as_ushort(h0) | ((uint32_t)__half_as_ushort(h1) << 16);
}
__device__ __forceinline__ uint32_t pack2h(float x0, float x1) {
    return (uint32_t)__half_as_ushort(__float2half_rn(x0)) |
           ((uint32_t)__half_as_ushort(__float2half_rn(x1)) << 16);
}

// ======== prep: E norms (unscaled) + scaled fp16 h/l split, swizzled ========
__global__ void vq_prep_e(const float* __restrict__ E) {
    int code = blockIdx.x, t = threadIdx.x;            // 64 threads, 4 k each
    float4 v = ((const float4*)(E + (size_t)code * CDIM))[t];
    float s = v.x * v.x + v.y * v.y + v.z * v.z + v.w * v.w;

    float xs[4] = {v.x * ESCALE, v.y * ESCALE, v.z * ESCALE, v.w * ESCALE};
    float r0, r1, r2, r3;
    uint32_t h01 = pack2(xs[0], xs[1], r0, r1);
    uint32_t h23 = pack2(xs[2], xs[3], r2, r3);
    uint32_t l01 = pack2h(r0, r1);
    uint32_t l23 = pack2h(r2, r3);

    int k0 = t * 4;
    int g  = k0 >> 3;
    uint32_t off = (uint32_t)code * 512 +
                   ((uint32_t)(g ^ (code & 7)) << 4) + (((uint32_t)k0 & 7) << 1);
    *(uint2*)((char*)g_Bh + off) = make_uint2(h01, h23);
    *(uint2*)((char*)g_Bl + off) = make_uint2(l01, l23);

    for (int o = 16; o > 0; o >>= 1) s += __shfl_down_sync(0xffffffffu, s, o);
    __shared__ float red[2];
    if ((t & 31) == 0) red[t >> 5] = s;
    __syncthreads();
    if (t == 0) g_ne[code] = red[0] + red[1];
}

// ======== prep: ||z||^2 (fixed ascending-k FMA order) + zero accumulators ========
__global__ void vq_prep_nz(const float* __restrict__ Z) {
    int v = blockIdx.x * 128 + threadIdx.x;
    if (v == 0) { g_loss = 0.0; g_fixcnt = 0; }
    int img = v >> 10, hw = v & 1023;
    const float* zp = Z + (size_t)img * CDIM * HW + hw;
    float nz = 0.f;
    for (int k = 0; k < CDIM; k++) {
        float x = zp[(size_t)k * HW];
        nz = fmaf(x, x, nz);
    }
    g_nz[v] = nz;
}

// ======== main: mma.sync fp16x3-split GEMM + argmin(+runner-up) + gather ========
__global__ __launch_bounds__(256, 1)
void vq_main(const float* __restrict__ Z, const float* __restrict__ E,
             float* __restrict__ out) {
    extern __shared__ __align__(16) char smem[];
    const uint32_t sb = smem_u32(smem);
    const int tid = threadIdx.x, lane = tid & 31, wid = tid >> 5;
    const int wm = wid & 3, wn = wid >> 2;              // 4m x 2n warp grid
    float* nes = (float*)(smem + SNE);

    for (int i = tid; i < KCODES; i += 256) nes[i] = g_ne[i];

    const int arow0 = wm * 32 + (lane & 7) + ((lane >> 3) & 1) * 8;
    const uint32_t arx  = ((uint32_t)(arow0 & 7)) << 4;
    const int akh = (lane >> 4) & 1;
    const uint32_t aoff0 = (uint32_t)arow0 * 512;
    const uint32_t aoff1 = aoff0 + 16 * 512;
    const int brow = wn * 16 + ((lane >> 4) & 1) * 8 + (lane & 7);
    const uint32_t brx = ((uint32_t)(brow & 7)) << 4;
    const int bkh = (lane >> 3) & 1;
    const uint32_t boff = (uint32_t)brow * 512;

    for (int mt = 0; mt < 2; mt++) {
        const int v0  = (blockIdx.x * 2 + mt) * 128;
        const int img = v0 >> 10;
        const int hw0 = v0 & 1023;
        const float* zimg = Z + (size_t)img * CDIM * HW;

        __syncthreads();
        // ---- stage A: z -> fp16 h/l split into swizzled smem ----
        {
            int row = tid & 127;
            int gb  = tid >> 7;
            const float* zp = zimg + hw0 + row;
            uint32_t abase = (uint32_t)row * 512;
            uint32_t rx = ((uint32_t)(row & 7)) << 4;
#pragma unroll 4
            for (int j = 0; j < 16; j++) {
                int g = gb + j * 2;
                float x[8];
#pragma unroll
                for (int i = 0; i < 8; i++) x[i] = zp[(size_t)(g * 8 + i) * HW];
                uint32_t hh[4], ll[4];
#pragma unroll
                for (int q = 0; q < 4; q++) {
                    float ra, rb;
                    hh[q] = pack2(x[2 * q], x[2 * q + 1], ra, rb);
                    ll[q] = pack2h(ra, rb);
                }
                uint32_t off = abase + ((((uint32_t)g) << 4) ^ rx);
                *(uint4*)(smem + SA_H + off) = make_uint4(hh[0], hh[1], hh[2], hh[3]);
                *(uint4*)(smem + SA_L + off) = make_uint4(ll[0], ll[1], ll[2], ll[3]);
            }
        }

        float best[4], second[4], nzr[4];
        int   bidx[4];
#pragma unroll
        for (int s = 0; s < 4; s++) {
            best[s] = 3.4e38f; second[s] = 3.4e38f; bidx[s] = 0;
            nzr[s] = g_nz[v0 + wm * 32 + (s >> 1) * 16 + (s & 1) * 8 + (lane >> 2)];
        }

        // ---- prologue: prefetch B chunk 0 ----
        {
            const char* sH = (const char*)g_Bh;
            const char* sL = (const char*)g_Bl;
            for (int i = tid; i < 1024; i += 256) {
                __pipeline_memcpy_async(smem + SB + i * 16,           sH + i * 16, 16);
                __pipeline_memcpy_async(smem + SB + 16384 + i * 16,   sL + i * 16, 16);
            }
            __pipeline_commit();
        }
        __syncthreads();

        for (int nc = 0; nc < 32; nc++) {
            const int b = nc & 1;
            if (nc + 1 < 32) {
                const char* sH = (const char*)g_Bh + (size_t)(nc + 1) * 32 * 512;
                const char* sL = (const char*)g_Bl + (size_t)(nc + 1) * 32 * 512;
                uint32_t db = (uint32_t)(SB + (1 - b) * 32768);
                for (int i = tid; i < 1024; i += 256) {
                    __pipeline_memcpy_async(smem + db + i * 16,         sH + i * 16, 16);
                    __pipeline_memcpy_async(smem + db + 16384 + i * 16, sL + i * 16, 16);
                }
                __pipeline_commit();
                __pipeline_wait_prior(1);
            } else {
                __pipeline_wait_prior(0);
            }
            __syncthreads();

            float acc[2][2][4];
#pragma unroll
            for (int mi = 0; mi < 2; mi++)
#pragma unroll
                for (int ni = 0; ni < 2; ni++)
#pragma unroll
                    for (int c = 0; c < 4; c++) acc[mi][ni][c] = 0.f;

            const uint32_t bH = sb + SB + b * 32768 + boff;
            const uint32_t bL = bH + 16384;
            const uint32_t aH0 = sb + SA_H + aoff0, aH1 = sb + SA_H + aoff1;
            const uint32_t aL0 = sb + SA_L + aoff0, aL1 = sb + SA_L + aoff1;

#pragma unroll
            for (int ks = 0; ks < 16; ks++) {
                uint32_t akc = (((uint32_t)(ks * 2 + akh)) << 4) ^ arx;
                uint32_t bkc = (((uint32_t)(ks * 2 + bkh)) << 4) ^ brx;
                uint32_t ah0[4], ah1[4], al0[4], al1[4], bh[4], bl[4];
                LDSM4(ah0, aH0 + akc);
                LDSM4(ah1, aH1 + akc);
                LDSM4(al0, aL0 + akc);
                LDSM4(al1, aL1 + akc);
                LDSM4(bh,  bH + bkc);
                LDSM4(bl,  bL + bkc);
#pragma unroll
                for (int ni = 0; ni < 2; ni++) {
                    MMA16816(acc[0][ni], ah0, bh[ni * 2], bh[ni * 2 + 1]);
                    MMA16816(acc[1][ni], ah1, bh[ni * 2], bh[ni * 2 + 1]);
                    MMA16816(acc[0][ni], ah0, bl[ni * 2], bl[ni * 2 + 1]);
                    MMA16816(acc[1][ni], ah1, bl[ni * 2], bl[ni * 2 + 1]);
                    MMA16816(acc[0][ni], al0, bh[ni * 2], bh[ni * 2 + 1]);
                    MMA16816(acc[1][ni], al1, bh[ni * 2], bh[ni * 2 + 1]);
                }
            }

            // ---- fold into running argmin + second-best, reference rounding chain ----
#pragma unroll
            for (int mi = 0; mi < 2; mi++)
#pragma unroll
                for (int ch = 0; ch < 2; ch++) {
                    int s = mi * 2 + ch;
#pragma unroll
                    for (int ni = 0; ni < 2; ni++)
#pragma unroll
                        for (int cl = 0; cl < 2; cl++) {
                            int code  = nc * 32 + wn * 16 + ni * 8 + (lane & 3) * 2 + cl;
                            float dot = acc[mi][ni][ch * 2 + cl] * EINV;
                            float d   = fmaf(-2.0f, dot, nzr[s]) + nes[code];
                            if (d < best[s]) { second[s] = best[s]; best[s] = d; bidx[s] = code; }
                            else if (d < second[s]) second[s] = d;
                        }
                }
            __syncthreads();
        }

        // ---- cross-lane then cross-warp merge of (best, idx, second) ----
#pragma unroll
        for (int s = 0; s < 4; s++) {
            float bd = best[s], sd = second[s]; int bi = bidx[s];
#pragma unroll
            for (int off = 1; off <= 2; off <<= 1) {
                float ob = __shfl_xor_sync(0xffffffffu, bd, off);
                float os = __shfl_xor_sync(0xffffffffu, sd, off);
                int   oi = __shfl_xor_sync(0xffffffffu, bi, off);
                if (ob < bd || (ob == bd && oi < bi)) {
                    sd = fminf(bd, os); bd = ob; bi = oi;
                } else {
                    sd = fminf(sd, ob);
                }
            }
            if ((lane & 3) == 0) {
                int row = wm * 32 + (s >> 1) * 16 + (s & 1) * 8 + (lane >> 2);
                ((float*)(smem + SBEST))[row * 2 + wn] = bd;
                ((float*)(smem + SSEC))[row * 2 + wn]  = sd;
                ((int*)(smem + SIDX))[row * 2 + wn]    = bi;
            }
        }
        __syncthreads();
        if (tid < 128) {
            float b0 = ((float*)(smem + SBEST))[tid * 2];
            float b1 = ((float*)(smem + SBEST))[tid * 2 + 1];
            float s0 = ((float*)(smem + SSEC))[tid * 2];
            float s1 = ((float*)(smem + SSEC))[tid * 2 + 1];
            int   i0 = ((int*)(smem + SIDX))[tid * 2];
            int   i1 = ((int*)(smem + SIDX))[tid * 2 + 1];
            float bb, ss; int ii;
            if (b1 < b0 || (b1 == b0 && i1 < i0)) { bb = b1; ii = i1; ss = fminf(b0, s1); }
            else                                  { bb = b0; ii = i0; ss = fminf(b1, s0); }
            ((int*)(smem + SROW))[tid] = ii;
            int row = v0 + tid;
            g_code[row] = ii;
            if (ss - bb <= FIX_EPS) {
                int p = atomicAdd(&g_fixcnt, 1);
                if (p < FIXCAP) g_fixlist[p] = row;
            }
        }
        __syncthreads();

        // ---- gather + loss: 2 threads per row, 128 channels each ----
        float lsum = 0.f;
        {
            int row = tid & 127, chh = tid >> 7;
            int code = ((int*)(smem + SROW))[row];
            const float4* er = (const float4*)(E + (size_t)code * CDIM) + chh * 32;
            const float* zp = zimg + (size_t)(chh * 128) * HW + hw0 + row;
            float* op = out + (size_t)img * CDIM * HW + (size_t)(chh * 128) * HW + hw0 + row;
#pragma unroll 4
            for (int q = 0; q < 32; q++) {
                float4 e4 = er[q];
                float z0 = zp[(size_t)(q * 4 + 0) * HW];
                float z1 = zp[(size_t)(q * 4 + 1) * HW];
                float z2 = zp[(size_t)(q * 4 + 2) * HW];
                float z3 = zp[(size_t)(q * 4 + 3) * HW];
                op[(size_t)(q * 4 + 0) * HW] = e4.x;
                op[(size_t)(q * 4 + 1) * HW] = e4.y;
                op[(size_t)(q * 4 + 2) * HW] = e4.z;
                op[(size_t)(q * 4 + 3) * HW] = e4.w;
                float d0 = z0 - e4.x, d1 = z1 - e4.y, d2 = z2 - e4.z, d3 = z3 - e4.w;
                lsum += d0 * d0 + d1 * d1 + d2 * d2 + d3 * d3;
            }
        }
        for (int o = 16; o > 0; o >>= 1) lsum += __shfl_down_sync(0xffffffffu, lsum, o);
        if (lane == 0) ((float*)(smem + SRED))[wid] = lsum;
        __syncthreads();
        if (tid == 0) {
            float t = 0.f;
            for (int w = 0; w < 8; w++) t += ((float*)(smem + SRED))[w];
            atomicAdd(&g_loss, (double)t);
        }
    }
}

// ======== fixup: exact fp32 rescore of flagged rows (all 1024 codes) ========
__global__ void __launch_bounds__(128, 1)
vq_fixup(const float* __restrict__ Z, const float* __restrict__ E,
         float* __restrict__ out) {
    __shared__ float4 esw4[64][32];   // [k4][code] E chunk, transposed
    __shared__ float4 zs4[64][4];     // [k4][row]
    __shared__ float  nzs[4];
    __shared__ int    rows[4];
    __shared__ int    newc[4];

    const int tid = threadIdx.x, lane = tid & 31, w = tid >> 5;
    int nf = g_fixcnt; if (nf > FIXCAP) nf = FIXCAP;
    const int ntile = (nf + 3) >> 2;

    for (int tile = blockIdx.x; tile < ntile; tile += gridDim.x) {
        __syncthreads();
        if (tid < 4) {
            int li = tile * 4 + tid;
            int r = (li < nf) ? g_fixlist[li] : -1;
            rows[tid] = r;
            nzs[tid] = (r >= 0) ? g_nz[r] : 0.f;
        }
        __syncthreads();
        // stage z rows (transposed float4 layout)
        for (int i = tid; i < 1024; i += 128) {
            int rr = i >> 8, k = i & 255;
            int r = rows[rr];
            float v = 0.f;
            if (r >= 0)
                v = Z[(size_t)(r >> 10) * (CDIM * HW) + (size_t)k * HW + (r & 1023)];
            ((float*)zs4)[(k >> 2) * 16 + rr * 4 + (k & 3)] = v;
        }

        float bd = 3.4e38f; int bi = 0;
        for (int ch = 0; ch < 32; ch++) {
            __syncthreads();
            for (int i = tid; i < 2048; i += 128) {
                int c = i >> 6, k4 = i & 63;
                esw4[k4][c] = __ldg((const float4*)(E + (size_t)(ch * 32 + c) * CDIM) + k4);
            }
            __syncthreads();
            float dot = 0.f;
#pragma unroll 16
            for (int k4 = 0; k4 < 64; k4++) {
                float4 zv = zs4[k4][w];
                float4 ev = esw4[k4][lane];
                dot = fmaf(zv.x, ev.x, dot);
                dot = fmaf(zv.y, ev.y, dot);
                dot = fmaf(zv.z, ev.z, dot);
                dot = fmaf(zv.w, ev.w, dot);
            }
            float d = fmaf(-2.0f, dot, nzs[w]) + __ldg(&g_ne[ch * 32 + lane]);
            int code = ch * 32 + lane;
            if (d < bd) { bd = d; bi = code; }   // per-thread codes ascend
        }
        // warp argmin across the 32 codes-per-chunk lanes, lowest index on tie
#pragma unroll
        for (int off = 16; off > 0; off >>= 1) {
            float od = __shfl_xor_sync(0xffffffffu, bd, off);
            int   oi = __shfl_xor_sync(0xffffffffu, bi, off);
            if (od < bd || (od == bd && oi < bi)) { bd = od; bi = oi; }
        }
        if (lane == 0) newc[w] = bi;
        __syncthreads();

        int r = rows[w];
        if (r >= 0) {
            int nc_ = newc[w], oc = g_code[r];
            if (nc_ != oc) {
                int img = r >> 10, hw = r & 1023;
                const float* en = E + (size_t)nc_ * CDIM;
                const float* eo = E + (size_t)oc * CDIM;
                float delta = 0.f;
#pragma unroll
                for (int q = 0; q < 8; q++) {
                    int k = lane * 8 + q;
                    float zv = ((float*)zs4)[(k >> 2) * 16 + w * 4 + (k & 3)];
                    float a = en[k], bo = eo[k];
                    out[(size_t)img * (CDIM * HW) + (size_t)k * HW + hw] = a;
                    float dn = zv - a, dl = zv - bo;
                    delta += dn * dn - dl * dl;
                }
                for (int o = 16; o > 0; o >>= 1)
                    delta += __shfl_down_sync(0xffffffffu, delta, o);
                if (lane == 0) {
                    atomicAdd(&g_loss, (double)delta);
                    g_code[r] = nc_;
                }
            }
        }
    }
}

// ======== finalize scalars ========
__global__ void vq_final(float* out, int out_size) {
    if (out_size >= QELEMS + 1) {
        float vq = (float)(g_loss / (double)QELEMS);
        out[QELEMS] = vq;
        if (out_size >= QELEMS + 2) out[QELEMS + 1] = 0.25f * vq;
    }
}

extern "C" void kernel_launch(void* const* d_in, const int* in_sizes, int n_in,
                              void* d_out, int out_size) {
    const float* Z = (const float*)d_in[0];
    const float* E = (const float*)d_in[1];
    if (n_in >= 2 && in_sizes[0] == KCODES * CDIM && in_sizes[1] == QELEMS) {
        const float* t = Z; Z = E; E = t;
    }
    float* out = (float*)d_out;

    cudaFuncSetAttribute(vq_main, cudaFuncAttributeMaxDynamicSharedMemorySize, SMEM_TOTAL);
    vq_prep_e<<<KCODES, 64>>>(E);
    vq_prep_nz<<<NVEC / 128, 128>>>(Z);
    vq_main<<<128, 256, SMEM_TOTAL>>>(Z, E, out);
    vq_fixup<<<128, 128>>>(Z, E, out);
    vq_final<<<1, 1>>>(out, out_size);
}

// round 10
// speedup vs baseline: 3.1827x; 1.3508x over previous
#include <cuda_runtime.h>
#include <cuda_fp16.h>
#include <cuda_pipeline.h>
#include <cstdint>
#include <cstddef>

#define CDIM   256
#define KCODES 1024
#define HW     1024
#define NVEC   32768
#define QELEMS (NVEC * CDIM)

#define ESCALE 2048.0f          // 2^11, exact scaling of E before fp16 split
#define EINV   (1.0f / 2048.0f)

#define FIXCAP  4096
#define FIXBCAP 256

// ---- dynamic smem layout (bytes) ----
#define SA_H   0                // A-high: 128 rows x 512B (256 fp16), swizzled
#define SA_L   65536            // A-low
#define SB     131072           // 2 buffers x (Bh 16KB + Bl 16KB)
#define SNE    196608           // 1024 floats
#define SB1    200704           // float[128][2]
#define SB2    201728           // float[128][2]
#define SB3    202752           // float[128][2]
#define SI1    203776           // int[128][2]
#define SI2    204800           // int[128][2]
#define SROW   205824           // int[128]
#define SRED   206336           // float[8]
#define SMEM_TOTAL 206848

__device__ float  g_ne[KCODES];
__device__ float  g_nz[NVEC];
__device__ double g_loss;
__device__ int    g_cntA, g_cntB;
__device__ int    g_fixA_row[FIXCAP], g_fixA_c1[FIXCAP], g_fixA_c2[FIXCAP];
__device__ int    g_fixB_row[FIXBCAP];
__device__ int    g_code[NVEC];
// E pre-split (scaled by 2^11), [code][k] fp16, 512B rows, XOR-swizzled 16B chunks
__device__ __align__(16) __half g_Bh[KCODES * CDIM];
__device__ __align__(16) __half g_Bl[KCODES * CDIM];

__device__ __forceinline__ uint32_t smem_u32(const void* p) {
    uint32_t a;
    asm("{ .reg .u64 t; cvta.to.shared.u64 t, %1; cvt.u32.u64 %0, t; }" : "=r"(a) : "l"(p));
    return a;
}
__device__ __forceinline__ float ulpf(float v) {
    return __int_as_float(__float_as_int(v) & 0x7f800000) * 1.1920929e-07f;
}

#define LDSM4(r, addr) \
    asm volatile("ldmatrix.sync.aligned.m8n8.x4.shared.b16 {%0,%1,%2,%3}, [%4];" \
        : "=r"((r)[0]), "=r"((r)[1]), "=r"((r)[2]), "=r"((r)[3]) : "r"(addr))

#define MMA16816(acc, a, b0, b1) \
    asm volatile("mma.sync.aligned.m16n8k16.row.col.f32.f16.f16.f32 " \
        "{%0,%1,%2,%3}, {%4,%5,%6,%7}, {%8,%9}, {%0,%1,%2,%3};" \
        : "+f"((acc)[0]), "+f"((acc)[1]), "+f"((acc)[2]), "+f"((acc)[3]) \
        : "r"((a)[0]), "r"((a)[1]), "r"((a)[2]), "r"((a)[3]), "r"(b0), "r"(b1))

__device__ __forceinline__ uint32_t pack2(float x0, float x1, float& r0, float& r1) {
    __half h0 = __float2half_rn(x0);
    __half h1 = __float2half_rn(x1);
    r0 = x0 - __half2float(h0);
    r1 = x1 - __half2float(h1);
    return (uint32_t)__half_as_ushort(h0) | ((uint32_t)__half_as_ushort(h1) << 16);
}
__device__ __forceinline__ uint32_t pack2h(float x0, float x1) {
    return (uint32_t)__half_as_ushort(__float2half_rn(x0)) |
           ((uint32_t)__half_as_ushort(__float2half_rn(x1)) << 16);
}

// merge two sorted (b1,i1,b2,i2,b3) triples, lexicographic (d, idx) order
__device__ __forceinline__ void merge3c(float& b1, int& i1, float& b2, int& i2, float& b3,
                                        float ob1, int oi1, float ob2, int oi2, float ob3) {
    float mb1 = b1, mb2 = b2, mb3 = b3;
    int   mi1 = i1, mi2 = i2;
    if (ob1 < mb1 || (ob1 == mb1 && oi1 < mi1)) {
        b1 = ob1; i1 = oi1;
        if (mb1 < ob2 || (mb1 == ob2 && mi1 < oi2)) {
            b2 = mb1; i2 = mi1; b3 = fminf(ob2, mb2);
        } else {
            b2 = ob2; i2 = oi2; b3 = fminf(ob3, mb1);
        }
    } else {
        if (ob1 < mb2 || (ob1 == mb2 && oi1 < mi2)) {
            b2 = ob1; i2 = oi1; b3 = fminf(mb2, ob2);
        } else {
            b3 = fminf(mb3, ob1);
        }
    }
}

// ======== prep: E norms (unscaled) + scaled fp16 h/l split, swizzled ========
__global__ void vq_prep_e(const float* __restrict__ E) {
    int code = blockIdx.x, t = threadIdx.x;            // 64 threads, 4 k each
    float4 v = ((const float4*)(E + (size_t)code * CDIM))[t];
    float s = v.x * v.x + v.y * v.y + v.z * v.z + v.w * v.w;

    float xs[4] = {v.x * ESCALE, v.y * ESCALE, v.z * ESCALE, v.w * ESCALE};
    float r0, r1, r2, r3;
    uint32_t h01 = pack2(xs[0], xs[1], r0, r1);
    uint32_t h23 = pack2(xs[2], xs[3], r2, r3);
    uint32_t l01 = pack2h(r0, r1);
    uint32_t l23 = pack2h(r2, r3);

    int k0 = t * 4;
    int g  = k0 >> 3;
    uint32_t off = (uint32_t)code * 512 +
                   ((uint32_t)(g ^ (code & 7)) << 4) + (((uint32_t)k0 & 7) << 1);
    *(uint2*)((char*)g_Bh + off) = make_uint2(h01, h23);
    *(uint2*)((char*)g_Bl + off) = make_uint2(l01, l23);

    for (int o = 16; o > 0; o >>= 1) s += __shfl_down_sync(0xffffffffu, s, o);
    __shared__ float red[2];
    if ((t & 31) == 0) red[t >> 5] = s;
    __syncthreads();
    if (t == 0) g_ne[code] = red[0] + red[1];
}

// ======== prep: ||z||^2 (fixed ascending-k FMA order) + zero accumulators ========
__global__ void vq_prep_nz(const float* __restrict__ Z) {
    int v = blockIdx.x * 128 + threadIdx.x;
    if (v == 0) { g_loss = 0.0; g_cntA = 0; g_cntB = 0; }
    int img = v >> 10, hw = v & 1023;
    const float* zp = Z + (size_t)img * CDIM * HW + hw;
    float nz = 0.f;
    for (int k = 0; k < CDIM; k++) {
        float x = zp[(size_t)k * HW];
        nz = fmaf(x, x, nz);
    }
    g_nz[v] = nz;
}

// ======== main: mma.sync fp16x3-split GEMM + top-3 argmin + gather ========
__global__ __launch_bounds__(256, 1)
void vq_main(const float* __restrict__ Z, const float* __restrict__ E,
             float* __restrict__ out) {
    extern __shared__ __align__(16) char smem[];
    const uint32_t sb = smem_u32(smem);
    const int tid = threadIdx.x, lane = tid & 31, wid = tid >> 5;
    const int wm = wid & 3, wn = wid >> 2;              // 4m x 2n warp grid
    float* nes = (float*)(smem + SNE);

    for (int i = tid; i < KCODES; i += 256) nes[i] = g_ne[i];

    const int arow0 = wm * 32 + (lane & 7) + ((lane >> 3) & 1) * 8;
    const uint32_t arx  = ((uint32_t)(arow0 & 7)) << 4;
    const int akh = (lane >> 4) & 1;
    const uint32_t aoff0 = (uint32_t)arow0 * 512;
    const uint32_t aoff1 = aoff0 + 16 * 512;
    const int brow = wn * 16 + ((lane >> 4) & 1) * 8 + (lane & 7);
    const uint32_t brx = ((uint32_t)(brow & 7)) << 4;
    const int bkh = (lane >> 3) & 1;
    const uint32_t boff = (uint32_t)brow * 512;

    for (int mt = 0; mt < 2; mt++) {
        const int v0  = (blockIdx.x * 2 + mt) * 128;
        const int img = v0 >> 10;
        const int hw0 = v0 & 1023;
        const float* zimg = Z + (size_t)img * CDIM * HW;

        __syncthreads();
        // ---- stage A: z -> fp16 h/l split into swizzled smem ----
        {
            int row = tid & 127;
            int gb  = tid >> 7;
            const float* zp = zimg + hw0 + row;
            uint32_t abase = (uint32_t)row * 512;
            uint32_t rx = ((uint32_t)(row & 7)) << 4;
#pragma unroll 4
            for (int j = 0; j < 16; j++) {
                int g = gb + j * 2;
                float x[8];
#pragma unroll
                for (int i = 0; i < 8; i++) x[i] = zp[(size_t)(g * 8 + i) * HW];
                uint32_t hh[4], ll[4];
#pragma unroll
                for (int q = 0; q < 4; q++) {
                    float ra, rb;
                    hh[q] = pack2(x[2 * q], x[2 * q + 1], ra, rb);
                    ll[q] = pack2h(ra, rb);
                }
                uint32_t off = abase + ((((uint32_t)g) << 4) ^ rx);
                *(uint4*)(smem + SA_H + off) = make_uint4(hh[0], hh[1], hh[2], hh[3]);
                *(uint4*)(smem + SA_L + off) = make_uint4(ll[0], ll[1], ll[2], ll[3]);
            }
        }

        float b1[4], b2[4], b3[4], nzr[4];
        int   i1[4], i2[4];
#pragma unroll
        for (int s = 0; s < 4; s++) {
            b1[s] = 3.4e38f; b2[s] = 3.4e38f; b3[s] = 3.4e38f; i1[s] = 0; i2[s] = 0;
            nzr[s] = g_nz[v0 + wm * 32 + (s >> 1) * 16 + (s & 1) * 8 + (lane >> 2)];
        }

        // ---- prologue: prefetch B chunk 0 ----
        {
            const char* sH = (const char*)g_Bh;
            const char* sL = (const char*)g_Bl;
            for (int i = tid; i < 1024; i += 256) {
                __pipeline_memcpy_async(smem + SB + i * 16,           sH + i * 16, 16);
                __pipeline_memcpy_async(smem + SB + 16384 + i * 16,   sL + i * 16, 16);
            }
            __pipeline_commit();
        }
        __syncthreads();   // A staged before mma

        for (int nc = 0; nc < 32; nc++) {
            const int b = nc & 1;
            if (nc + 1 < 32) {
                const char* sH = (const char*)g_Bh + (size_t)(nc + 1) * 32 * 512;
                const char* sL = (const char*)g_Bl + (size_t)(nc + 1) * 32 * 512;
                uint32_t db = (uint32_t)(SB + (1 - b) * 32768);
                for (int i = tid; i < 1024; i += 256) {
                    __pipeline_memcpy_async(smem + db + i * 16,         sH + i * 16, 16);
                    __pipeline_memcpy_async(smem + db + 16384 + i * 16, sL + i * 16, 16);
                }
                __pipeline_commit();
                __pipeline_wait_prior(1);
            } else {
                __pipeline_wait_prior(0);
            }
            __syncthreads();

            float acc[2][2][4];
#pragma unroll
            for (int mi = 0; mi < 2; mi++)
#pragma unroll
                for (int ni = 0; ni < 2; ni++)
#pragma unroll
                    for (int c = 0; c < 4; c++) acc[mi][ni][c] = 0.f;

            const uint32_t bH = sb + SB + b * 32768 + boff;
            const uint32_t bL = bH + 16384;
            const uint32_t aH0 = sb + SA_H + aoff0, aH1 = sb + SA_H + aoff1;
            const uint32_t aL0 = sb + SA_L + aoff0, aL1 = sb + SA_L + aoff1;

#pragma unroll
            for (int ks = 0; ks < 16; ks++) {
                uint32_t akc = (((uint32_t)(ks * 2 + akh)) << 4) ^ arx;
                uint32_t bkc = (((uint32_t)(ks * 2 + bkh)) << 4) ^ brx;
                uint32_t ah0[4], ah1[4], al0[4], al1[4], bh[4], bl[4];
                LDSM4(ah0, aH0 + akc);
                LDSM4(ah1, aH1 + akc);
                LDSM4(al0, aL0 + akc);
                LDSM4(al1, aL1 + akc);
                LDSM4(bh,  bH + bkc);
                LDSM4(bl,  bL + bkc);
#pragma unroll
                for (int ni = 0; ni < 2; ni++) {
                    MMA16816(acc[0][ni], ah0, bh[ni * 2], bh[ni * 2 + 1]);
                    MMA16816(acc[1][ni], ah1, bh[ni * 2], bh[ni * 2 + 1]);
                    MMA16816(acc[0][ni], ah0, bl[ni * 2], bl[ni * 2 + 1]);
                    MMA16816(acc[1][ni], ah1, bl[ni * 2], bl[ni * 2 + 1]);
                    MMA16816(acc[0][ni], al0, bh[ni * 2], bh[ni * 2 + 1]);
                    MMA16816(acc[1][ni], al1, bh[ni * 2], bh[ni * 2 + 1]);
                }
            }

            // ---- fold into running top-3, reference rounding chain ----
#pragma unroll
            for (int mi = 0; mi < 2; mi++)
#pragma unroll
                for (int ch = 0; ch < 2; ch++) {
                    int s = mi * 2 + ch;
#pragma unroll
                    for (int ni = 0; ni < 2; ni++)
#pragma unroll
                        for (int cl = 0; cl < 2; cl++) {
                            int code  = nc * 32 + wn * 16 + ni * 8 + (lane & 3) * 2 + cl;
                            float dot = acc[mi][ni][ch * 2 + cl] * EINV;
                            float d   = fmaf(-2.0f, dot, nzr[s]) + nes[code];
                            if (d < b1[s]) {
                                b3[s] = b2[s]; b2[s] = b1[s]; i2[s] = i1[s];
                                b1[s] = d; i1[s] = code;
                            } else if (d < b2[s]) {
                                b3[s] = b2[s]; b2[s] = d; i2[s] = code;
                            } else if (d < b3[s]) {
                                b3[s] = d;
                            }
                        }
                }
            __syncthreads();
        }

        // ---- cross-lane merge (xor 1,2) of the top-3 triples ----
#pragma unroll
        for (int s = 0; s < 4; s++) {
#pragma unroll
            for (int off = 1; off <= 2; off <<= 1) {
                float ob1 = __shfl_xor_sync(0xffffffffu, b1[s], off);
                float ob2 = __shfl_xor_sync(0xffffffffu, b2[s], off);
                float ob3 = __shfl_xor_sync(0xffffffffu, b3[s], off);
                int   oi1 = __shfl_xor_sync(0xffffffffu, i1[s], off);
                int   oi2 = __shfl_xor_sync(0xffffffffu, i2[s], off);
                merge3c(b1[s], i1[s], b2[s], i2[s], b3[s], ob1, oi1, ob2, oi2, ob3);
            }
            if ((lane & 3) == 0) {
                int row = wm * 32 + (s >> 1) * 16 + (s & 1) * 8 + (lane >> 2);
                ((float*)(smem + SB1))[row * 2 + wn] = b1[s];
                ((float*)(smem + SB2))[row * 2 + wn] = b2[s];
                ((float*)(smem + SB3))[row * 2 + wn] = b3[s];
                ((int*)(smem + SI1))[row * 2 + wn]   = i1[s];
                ((int*)(smem + SI2))[row * 2 + wn]   = i2[s];
            }
        }
        __syncthreads();
        if (tid < 128) {
            float a1 = ((float*)(smem + SB1))[tid * 2];
            float a2 = ((float*)(smem + SB2))[tid * 2];
            float a3 = ((float*)(smem + SB3))[tid * 2];
            int   x1 = ((int*)(smem + SI1))[tid * 2];
            int   x2 = ((int*)(smem + SI2))[tid * 2];
            merge3c(a1, x1, a2, x2, a3,
                    ((float*)(smem + SB1))[tid * 2 + 1],
                    ((int*)(smem + SI1))[tid * 2 + 1],
                    ((float*)(smem + SB2))[tid * 2 + 1],
                    ((int*)(smem + SI2))[tid * 2 + 1],
                    ((float*)(smem + SB3))[tid * 2 + 1]);
            ((int*)(smem + SROW))[tid] = x1;
            int row = v0 + tid;
            g_code[row] = x1;
            if (a3 - a1 <= 3.0f * ulpf(a3)) {
                int p = atomicAdd(&g_cntB, 1);
                if (p < FIXBCAP) g_fixB_row[p] = row;
            } else if (a2 - a1 <= 3.0f * ulpf(a2)) {
                int p = atomicAdd(&g_cntA, 1);
                if (p < FIXCAP) {
                    g_fixA_row[p] = row; g_fixA_c1[p] = x1; g_fixA_c2[p] = x2;
                }
            }
        }
        __syncthreads();

        // ---- gather + loss: 2 threads per row, 128 channels each ----
        float lsum = 0.f;
        {
            int row = tid & 127, chh = tid >> 7;
            int code = ((int*)(smem + SROW))[row];
            const float4* er = (const float4*)(E + (size_t)code * CDIM) + chh * 32;
            const float* zp = zimg + (size_t)(chh * 128) * HW + hw0 + row;
            float* op = out + (size_t)img * CDIM * HW + (size_t)(chh * 128) * HW + hw0 + row;
#pragma unroll 4
            for (int q = 0; q < 32; q++) {
                float4 e4 = er[q];
                float z0 = zp[(size_t)(q * 4 + 0) * HW];
                float z1 = zp[(size_t)(q * 4 + 1) * HW];
                float z2 = zp[(size_t)(q * 4 + 2) * HW];
                float z3 = zp[(size_t)(q * 4 + 3) * HW];
                op[(size_t)(q * 4 + 0) * HW] = e4.x;
                op[(size_t)(q * 4 + 1) * HW] = e4.y;
                op[(size_t)(q * 4 + 2) * HW] = e4.z;
                op[(size_t)(q * 4 + 3) * HW] = e4.w;
                float d0 = z0 - e4.x, d1 = z1 - e4.y, d2 = z2 - e4.z, d3 = z3 - e4.w;
                lsum += d0 * d0 + d1 * d1 + d2 * d2 + d3 * d3;
            }
        }
        for (int o = 16; o > 0; o >>= 1) lsum += __shfl_down_sync(0xffffffffu, lsum, o);
        if (lane == 0) ((float*)(smem + SRED))[wid] = lsum;
        __syncthreads();
        if (tid == 0) {
            float t = 0.f;
            for (int w = 0; w < 8; w++) t += ((float*)(smem + SRED))[w];
            atomicAdd(&g_loss, (double)t);
        }
    }
}

// ======== fix A: exact 2-candidate compare, one warp per flagged row ========
__global__ void __launch_bounds__(128, 8)
vq_fixA(const float* __restrict__ Z, const float* __restrict__ E,
        float* __restrict__ out) {
    const int lane = threadIdx.x & 31;
    const int gw   = (blockIdx.x * blockDim.x + threadIdx.x) >> 5;
    const int nw   = (gridDim.x * blockDim.x) >> 5;
    int nf = g_cntA; if (nf > FIXCAP) nf = FIXCAP;

    for (int li = gw; li < nf; li += nw) {
        int r  = g_fixA_row[li];
        int c1 = g_fixA_c1[li], c2 = g_fixA_c2[li];
        int img = r >> 10, hw = r & 1023;
        const float* zp = Z + (size_t)img * (CDIM * HW) + hw;
        const float* e1 = E + (size_t)c1 * CDIM;
        const float* e2 = E + (size_t)c2 * CDIM;

        float zv[8], p1 = 0.f, p2 = 0.f;
#pragma unroll
        for (int q = 0; q < 8; q++) {
            int k = lane * 8 + q;
            zv[q] = zp[(size_t)k * HW];
            p1 = fmaf(zv[q], e1[k], p1);
            p2 = fmaf(zv[q], e2[k], p2);
        }
#pragma unroll
        for (int o = 16; o > 0; o >>= 1) {
            p1 += __shfl_xor_sync(0xffffffffu, p1, o);
            p2 += __shfl_xor_sync(0xffffffffu, p2, o);
        }
        int win = 0;
        if (lane == 0) {
            float nz = g_nz[r];
            float d1 = fmaf(-2.0f, p1, nz) + g_ne[c1];
            float d2 = fmaf(-2.0f, p2, nz) + g_ne[c2];
            win = (d2 < d1 || (d2 == d1 && c2 < c1)) ? c2 : c1;
        }
        win = __shfl_sync(0xffffffffu, win, 0);
        if (win != c1) {
            const float* en = E + (size_t)win * CDIM;
            float delta = 0.f;
#pragma unroll
            for (int q = 0; q < 8; q++) {
                int k = lane * 8 + q;
                float a = en[k], bo = e1[k];
                out[(size_t)img * (CDIM * HW) + (size_t)k * HW + hw] = a;
                float dn = zv[q] - a, dl = zv[q] - bo;
                delta += dn * dn - dl * dl;
            }
#pragma unroll
            for (int o = 16; o > 0; o >>= 1)
                delta += __shfl_xor_sync(0xffffffffu, delta, o);
            if (lane == 0) {
                atomicAdd(&g_loss, (double)delta);
                g_code[r] = win;
            }
        }
    }
}

// ======== fix B: full 1024-code exact rescan, one block per rare row ========
__global__ void __launch_bounds__(256, 1)
vq_fixB(const float* __restrict__ Z, const float* __restrict__ E,
        float* __restrict__ out) {
    __shared__ float zs[CDIM];
    __shared__ float sd[256];
    __shared__ int   si[256];
    const int tid = threadIdx.x;
    int nb = g_cntB; if (nb > FIXBCAP) nb = FIXBCAP;

    for (int li = blockIdx.x; li < nb; li += gridDim.x) {
        int r = g_fixB_row[li];
        int img = r >> 10, hw = r & 1023;
        const float* zp = Z + (size_t)img * (CDIM * HW) + hw;
        __syncthreads();
        if (tid < 256) zs[tid] = zp[(size_t)tid * HW];
        __syncthreads();
        float nz = g_nz[r];

        float bd = 3.4e38f; int bi = 0;
#pragma unroll
        for (int q = 0; q < 4; q++) {
            int c = tid * 4 + q;
            const float4* ev = (const float4*)(E + (size_t)c * CDIM);
            const float4* z4 = (const float4*)zs;
            float dot = 0.f;
#pragma unroll 8
            for (int k4 = 0; k4 < 64; k4++) {
                float4 e4 = ev[k4], zq = z4[k4];
                dot = fmaf(zq.x, e4.x, dot);
                dot = fmaf(zq.y, e4.y, dot);
                dot = fmaf(zq.z, e4.z, dot);
                dot = fmaf(zq.w, e4.w, dot);
            }
            float d = fmaf(-2.0f, dot, nz) + g_ne[c];
            if (d < bd) { bd = d; bi = c; }
        }
        sd[tid] = bd; si[tid] = bi;
        __syncthreads();
        for (int st = 128; st > 0; st >>= 1) {
            if (tid < st) {
                float od = sd[tid + st]; int oi = si[tid + st];
                if (od < sd[tid] || (od == sd[tid] && oi < si[tid])) {
                    sd[tid] = od; si[tid] = oi;
                }
            }
            __syncthreads();
        }
        int w = si[0], oc = g_code[r];
        __syncthreads();
        if (w != oc) {
            const float* en = E + (size_t)w * CDIM;
            const float* eo = E + (size_t)oc * CDIM;
            float delta = 0.f;
            if (tid < 256) {
                float a = en[tid], bo = eo[tid];
                float zvv = zs[tid];
                out[(size_t)img * (CDIM * HW) + (size_t)tid * HW + hw] = a;
                float dn = zvv - a, dl = zvv - bo;
                delta = dn * dn - dl * dl;
            }
            for (int o = 16; o > 0; o >>= 1)
                delta += __shfl_xor_sync(0xffffffffu, delta, o);
            __syncthreads();
            if ((tid & 31) == 0) sd[tid >> 5] = delta;
            __syncthreads();
            if (tid == 0) {
                float t = 0.f;
                for (int ww = 0; ww < 8; ww++) t += sd[ww];
                atomicAdd(&g_loss, (double)t);
                g_code[r] = w;
            }
        }
        __syncthreads();
    }
}

// ======== finalize scalars ========
__global__ void vq_final(float* out, int out_size) {
    if (out_size >= QELEMS + 1) {
        float vq = (float)(g_loss / (double)QELEMS);
        out[QELEMS] = vq;
        if (out_size >= QELEMS + 2) out[QELEMS + 1] = 0.25f * vq;
    }
}

extern "C" void kernel_launch(void* const* d_in, const int* in_sizes, int n_in,
                              void* d_out, int out_size) {
    const float* Z = (const float*)d_in[0];
    const float* E = (const float*)d_in[1];
    if (n_in >= 2 && in_sizes[0] == KCODES * CDIM && in_sizes[1] == QELEMS) {
        const float* t = Z; Z = E; E = t;
    }
    float* out = (float*)d_out;

    cudaFuncSetAttribute(vq_main, cudaFuncAttributeMaxDynamicSharedMemorySize, SMEM_TOTAL);
    vq_prep_e<<<KCODES, 64>>>(E);
    vq_prep_nz<<<NVEC / 128, 128>>>(Z);
    vq_main<<<128, 256, SMEM_TOTAL>>>(Z, E, out);
    vq_fixA<<<128, 128>>>(Z, E, out);
    vq_fixB<<<32, 256>>>(Z, E, out);
    vq_final<<<1, 1>>>(out, out_size);
}

// round 11
// speedup vs baseline: 5.1886x; 1.6302x over previous
#include <cuda_runtime.h>
#include <cuda_fp16.h>
#include <cuda_pipeline.h>
#include <cstdint>
#include <cstddef>

#define CDIM   256
#define KCODES 1024
#define HW     1024
#define NVEC   32768
#define QELEMS (NVEC * CDIM)

#define ESCALE 2048.0f          // 2^11, exact scaling of E before fp16 round
#define EINV   (1.0f / 2048.0f)

#define FIXCAP  8192
#define FIXBCAP 512
#define WIN_ULP 8.0f            // flag window: 8 d-grid cells (>30 sigma of hh-only error)

// ---- dynamic smem layout (bytes) ----
#define SA_H   0                // A-high: 128 rows x 512B (256 fp16), swizzled
#define SB     65536            // 2 buffers x 16KB (Bh only)
#define SNE    98304            // 1024 floats
#define SB1    102400           // float[128][2]
#define SB2    103424
#define SB3    104448
#define SI1    105472
#define SI2    106496
#define SROW   107520           // int[128]
#define SRED   108032           // float[8]
#define SMEM_TOTAL 108544

__device__ float  g_ne[KCODES];
__device__ float  g_nz[NVEC];
__device__ double g_loss;
__device__ int    g_cntA, g_cntB;
__device__ int    g_fixA_row[FIXCAP], g_fixA_c1[FIXCAP], g_fixA_c2[FIXCAP];
__device__ int    g_fixB_row[FIXBCAP];
__device__ int    g_code[NVEC];
// E high-split (scaled by 2^11), [code][k] fp16, 512B rows, XOR-swizzled 16B chunks
__device__ __align__(16) __half g_Bh[KCODES * CDIM];

__device__ __forceinline__ uint32_t smem_u32(const void* p) {
    uint32_t a;
    asm("{ .reg .u64 t; cvta.to.shared.u64 t, %1; cvt.u32.u64 %0, t; }" : "=r"(a) : "l"(p));
    return a;
}
__device__ __forceinline__ float ulpf(float v) {
    return __int_as_float(__float_as_int(v) & 0x7f800000) * 1.1920929e-07f;
}

#define LDSM4(r, addr) \
    asm volatile("ldmatrix.sync.aligned.m8n8.x4.shared.b16 {%0,%1,%2,%3}, [%4];" \
        : "=r"((r)[0]), "=r"((r)[1]), "=r"((r)[2]), "=r"((r)[3]) : "r"(addr))

#define MMA16816(acc, a, b0, b1) \
    asm volatile("mma.sync.aligned.m16n8k16.row.col.f32.f16.f16.f32 " \
        "{%0,%1,%2,%3}, {%4,%5,%6,%7}, {%8,%9}, {%0,%1,%2,%3};" \
        : "+f"((acc)[0]), "+f"((acc)[1]), "+f"((acc)[2]), "+f"((acc)[3]) \
        : "r"((a)[0]), "r"((a)[1]), "r"((a)[2]), "r"((a)[3]), "r"(b0), "r"(b1))

__device__ __forceinline__ uint32_t pack2h(float x0, float x1) {
    return (uint32_t)__half_as_ushort(__float2half_rn(x0)) |
           ((uint32_t)__half_as_ushort(__float2half_rn(x1)) << 16);
}

// merge two sorted (b1,i1,b2,i2,b3) triples, lexicographic (d, idx) order
__device__ __forceinline__ void merge3c(float& b1, int& i1, float& b2, int& i2, float& b3,
                                        float ob1, int oi1, float ob2, int oi2, float ob3) {
    float mb1 = b1, mb2 = b2, mb3 = b3;
    int   mi1 = i1, mi2 = i2;
    if (ob1 < mb1 || (ob1 == mb1 && oi1 < mi1)) {
        b1 = ob1; i1 = oi1;
        if (mb1 < ob2 || (mb1 == ob2 && mi1 < oi2)) {
            b2 = mb1; i2 = mi1; b3 = fminf(ob2, mb2);
        } else {
            b2 = ob2; i2 = oi2; b3 = fminf(ob3, mb1);
        }
    } else {
        if (ob1 < mb2 || (ob1 == mb2 && oi1 < mi2)) {
            b2 = ob1; i2 = oi1; b3 = fminf(mb2, ob2);
        } else {
            b3 = fminf(mb3, ob1);
        }
    }
}

// ======== prep: E norms (unscaled) + scaled fp16 high-split, swizzled ========
__global__ void vq_prep_e(const float* __restrict__ E) {
    int code = blockIdx.x, t = threadIdx.x;            // 64 threads, 4 k each
    float4 v = ((const float4*)(E + (size_t)code * CDIM))[t];
    float s = v.x * v.x + v.y * v.y + v.z * v.z + v.w * v.w;

    uint32_t h01 = pack2h(v.x * ESCALE, v.y * ESCALE);
    uint32_t h23 = pack2h(v.z * ESCALE, v.w * ESCALE);

    int k0 = t * 4;
    int g  = k0 >> 3;
    uint32_t off = (uint32_t)code * 512 +
                   ((uint32_t)(g ^ (code & 7)) << 4) + (((uint32_t)k0 & 7) << 1);
    *(uint2*)((char*)g_Bh + off) = make_uint2(h01, h23);

    for (int o = 16; o > 0; o >>= 1) s += __shfl_down_sync(0xffffffffu, s, o);
    __shared__ float red[2];
    if ((t & 31) == 0) red[t >> 5] = s;
    __syncthreads();
    if (t == 0) g_ne[code] = red[0] + red[1];
}

// ======== prep: ||z||^2 (fixed ascending-k FMA order) + zero accumulators ========
__global__ void vq_prep_nz(const float* __restrict__ Z) {
    int v = blockIdx.x * 128 + threadIdx.x;
    if (v == 0) { g_loss = 0.0; g_cntA = 0; g_cntB = 0; }
    int img = v >> 10, hw = v & 1023;
    const float* zp = Z + (size_t)img * CDIM * HW + hw;
    float nz = 0.f;
    for (int k = 0; k < CDIM; k++) {
        float x = zp[(size_t)k * HW];
        nz = fmaf(x, x, nz);
    }
    g_nz[v] = nz;
}

// ======== main: mma.sync hh-pass GEMM + top-3 argmin + gather, occ 2 ========
__global__ __launch_bounds__(256, 2)
void vq_main(const float* __restrict__ Z, const float* __restrict__ E,
             float* __restrict__ out) {
    extern __shared__ __align__(16) char smem[];
    const uint32_t sb = smem_u32(smem);
    const int tid = threadIdx.x, lane = tid & 31, wid = tid >> 5;
    const int wm = wid & 3, wn = wid >> 2;              // 4m x 2n warp grid
    float* nes = (float*)(smem + SNE);

    for (int i = tid; i < KCODES; i += 256) nes[i] = g_ne[i];

    const int arow0 = wm * 32 + (lane & 7) + ((lane >> 3) & 1) * 8;
    const uint32_t arx  = ((uint32_t)(arow0 & 7)) << 4;
    const int akh = (lane >> 4) & 1;
    const uint32_t aoff0 = (uint32_t)arow0 * 512;
    const uint32_t aoff1 = aoff0 + 16 * 512;
    const int brow = wn * 16 + ((lane >> 4) & 1) * 8 + (lane & 7);
    const uint32_t brx = ((uint32_t)(brow & 7)) << 4;
    const int bkh = (lane >> 3) & 1;
    const uint32_t boff = (uint32_t)brow * 512;

    const int v0  = blockIdx.x * 128;
    const int img = v0 >> 10;
    const int hw0 = v0 & 1023;
    const float* zimg = Z + (size_t)img * CDIM * HW;

    // ---- stage A: z -> fp16 high-split into swizzled smem ----
    {
        int row = tid & 127;
        int gb  = tid >> 7;
        const float* zp = zimg + hw0 + row;
        uint32_t abase = (uint32_t)row * 512;
        uint32_t rx = ((uint32_t)(row & 7)) << 4;
#pragma unroll 4
        for (int j = 0; j < 16; j++) {
            int g = gb + j * 2;
            float x[8];
#pragma unroll
            for (int i = 0; i < 8; i++) x[i] = zp[(size_t)(g * 8 + i) * HW];
            uint32_t hh[4];
#pragma unroll
            for (int q = 0; q < 4; q++) hh[q] = pack2h(x[2 * q], x[2 * q + 1]);
            uint32_t off = abase + ((((uint32_t)g) << 4) ^ rx);
            *(uint4*)(smem + SA_H + off) = make_uint4(hh[0], hh[1], hh[2], hh[3]);
        }
    }

    float b1[4], b2[4], b3[4], nzr[4];
    int   i1[4], i2[4];
#pragma unroll
    for (int s = 0; s < 4; s++) {
        b1[s] = 3.4e38f; b2[s] = 3.4e38f; b3[s] = 3.4e38f; i1[s] = 0; i2[s] = 0;
        nzr[s] = g_nz[v0 + wm * 32 + (s >> 1) * 16 + (s & 1) * 8 + (lane >> 2)];
    }

    // ---- prologue: prefetch B chunk 0 ----
    {
        const char* sH = (const char*)g_Bh;
        for (int i = tid; i < 1024; i += 256)
            __pipeline_memcpy_async(smem + SB + i * 16, sH + i * 16, 16);
        __pipeline_commit();
    }
    __syncthreads();   // A staged before mma

    for (int nc = 0; nc < 32; nc++) {
        const int b = nc & 1;
        if (nc + 1 < 32) {
            const char* sH = (const char*)g_Bh + (size_t)(nc + 1) * 32 * 512;
            uint32_t db = (uint32_t)(SB + (1 - b) * 16384);
            for (int i = tid; i < 1024; i += 256)
                __pipeline_memcpy_async(smem + db + i * 16, sH + i * 16, 16);
            __pipeline_commit();
            __pipeline_wait_prior(1);
        } else {
            __pipeline_wait_prior(0);
        }
        __syncthreads();

        float acc[2][2][4];
#pragma unroll
        for (int mi = 0; mi < 2; mi++)
#pragma unroll
            for (int ni = 0; ni < 2; ni++)
#pragma unroll
                for (int c = 0; c < 4; c++) acc[mi][ni][c] = 0.f;

        const uint32_t bH = sb + SB + b * 16384 + boff;
        const uint32_t aH0 = sb + SA_H + aoff0, aH1 = sb + SA_H + aoff1;

#pragma unroll
        for (int ks = 0; ks < 16; ks++) {
            uint32_t akc = (((uint32_t)(ks * 2 + akh)) << 4) ^ arx;
            uint32_t bkc = (((uint32_t)(ks * 2 + bkh)) << 4) ^ brx;
            uint32_t ah0[4], ah1[4], bh[4];
            LDSM4(ah0, aH0 + akc);
            LDSM4(ah1, aH1 + akc);
            LDSM4(bh,  bH + bkc);
#pragma unroll
            for (int ni = 0; ni < 2; ni++) {
                MMA16816(acc[0][ni], ah0, bh[ni * 2], bh[ni * 2 + 1]);
                MMA16816(acc[1][ni], ah1, bh[ni * 2], bh[ni * 2 + 1]);
            }
        }

        // ---- fold into running top-3, reference rounding chain ----
#pragma unroll
        for (int mi = 0; mi < 2; mi++)
#pragma unroll
            for (int ch = 0; ch < 2; ch++) {
                int s = mi * 2 + ch;
#pragma unroll
                for (int ni = 0; ni < 2; ni++)
#pragma unroll
                    for (int cl = 0; cl < 2; cl++) {
                        int code  = nc * 32 + wn * 16 + ni * 8 + (lane & 3) * 2 + cl;
                        float dot = acc[mi][ni][ch * 2 + cl] * EINV;
                        float d   = fmaf(-2.0f, dot, nzr[s]) + nes[code];
                        if (d < b1[s]) {
                            b3[s] = b2[s]; b2[s] = b1[s]; i2[s] = i1[s];
                            b1[s] = d; i1[s] = code;
                        } else if (d < b2[s]) {
                            b3[s] = b2[s]; b2[s] = d; i2[s] = code;
                        } else if (d < b3[s]) {
                            b3[s] = d;
                        }
                    }
            }
        __syncthreads();
    }

    // ---- cross-lane merge (xor 1,2) of the top-3 triples ----
#pragma unroll
    for (int s = 0; s < 4; s++) {
#pragma unroll
        for (int off = 1; off <= 2; off <<= 1) {
            float ob1 = __shfl_xor_sync(0xffffffffu, b1[s], off);
            float ob2 = __shfl_xor_sync(0xffffffffu, b2[s], off);
            float ob3 = __shfl_xor_sync(0xffffffffu, b3[s], off);
            int   oi1 = __shfl_xor_sync(0xffffffffu, i1[s], off);
            int   oi2 = __shfl_xor_sync(0xffffffffu, i2[s], off);
            merge3c(b1[s], i1[s], b2[s], i2[s], b3[s], ob1, oi1, ob2, oi2, ob3);
        }
        if ((lane & 3) == 0) {
            int row = wm * 32 + (s >> 1) * 16 + (s & 1) * 8 + (lane >> 2);
            ((float*)(smem + SB1))[row * 2 + wn] = b1[s];
            ((float*)(smem + SB2))[row * 2 + wn] = b2[s];
            ((float*)(smem + SB3))[row * 2 + wn] = b3[s];
            ((int*)(smem + SI1))[row * 2 + wn]   = i1[s];
            ((int*)(smem + SI2))[row * 2 + wn]   = i2[s];
        }
    }
    __syncthreads();
    if (tid < 128) {
        float a1 = ((float*)(smem + SB1))[tid * 2];
        float a2 = ((float*)(smem + SB2))[tid * 2];
        float a3 = ((float*)(smem + SB3))[tid * 2];
        int   x1 = ((int*)(smem + SI1))[tid * 2];
        int   x2 = ((int*)(smem + SI2))[tid * 2];
        merge3c(a1, x1, a2, x2, a3,
                ((float*)(smem + SB1))[tid * 2 + 1],
                ((int*)(smem + SI1))[tid * 2 + 1],
                ((float*)(smem + SB2))[tid * 2 + 1],
                ((int*)(smem + SI2))[tid * 2 + 1],
                ((float*)(smem + SB3))[tid * 2 + 1]);
        ((int*)(smem + SROW))[tid] = x1;
        int row = v0 + tid;
        g_code[row] = x1;
        if (a3 - a1 <= WIN_ULP * ulpf(a3)) {
            int p = atomicAdd(&g_cntB, 1);
            if (p < FIXBCAP) g_fixB_row[p] = row;
        } else if (a2 - a1 <= WIN_ULP * ulpf(a2)) {
            int p = atomicAdd(&g_cntA, 1);
            if (p < FIXCAP) {
                g_fixA_row[p] = row; g_fixA_c1[p] = x1; g_fixA_c2[p] = x2;
            }
        }
    }
    __syncthreads();

    // ---- gather + loss: 2 threads per row, 128 channels each ----
    float lsum = 0.f;
    {
        int row = tid & 127, chh = tid >> 7;
        int code = ((int*)(smem + SROW))[row];
        const float4* er = (const float4*)(E + (size_t)code * CDIM) + chh * 32;
        const float* zp = zimg + (size_t)(chh * 128) * HW + hw0 + row;
        float* op = out + (size_t)img * CDIM * HW + (size_t)(chh * 128) * HW + hw0 + row;
#pragma unroll 4
        for (int q = 0; q < 32; q++) {
            float4 e4 = er[q];
            float z0 = zp[(size_t)(q * 4 + 0) * HW];
            float z1 = zp[(size_t)(q * 4 + 1) * HW];
            float z2 = zp[(size_t)(q * 4 + 2) * HW];
            float z3 = zp[(size_t)(q * 4 + 3) * HW];
            op[(size_t)(q * 4 + 0) * HW] = e4.x;
            op[(size_t)(q * 4 + 1) * HW] = e4.y;
            op[(size_t)(q * 4 + 2) * HW] = e4.z;
            op[(size_t)(q * 4 + 3) * HW] = e4.w;
            float d0 = z0 - e4.x, d1 = z1 - e4.y, d2 = z2 - e4.z, d3 = z3 - e4.w;
            lsum += d0 * d0 + d1 * d1 + d2 * d2 + d3 * d3;
        }
    }
    for (int o = 16; o > 0; o >>= 1) lsum += __shfl_down_sync(0xffffffffu, lsum, o);
    if (lane == 0) ((float*)(smem + SRED))[wid] = lsum;
    __syncthreads();
    if (tid == 0) {
        float t = 0.f;
        for (int w = 0; w < 8; w++) t += ((float*)(smem + SRED))[w];
        atomicAdd(&g_loss, (double)t);
    }
}

// ======== fix A: exact 2-candidate compare, one warp per flagged row ========
__global__ void __launch_bounds__(128, 8)
vq_fixA(const float* __restrict__ Z, const float* __restrict__ E,
        float* __restrict__ out) {
    const int lane = threadIdx.x & 31;
    const int gw   = (blockIdx.x * blockDim.x + threadIdx.x) >> 5;
    const int nw   = (gridDim.x * blockDim.x) >> 5;
    int nf = g_cntA; if (nf > FIXCAP) nf = FIXCAP;

    for (int li = gw; li < nf; li += nw) {
        int r  = g_fixA_row[li];
        int c1 = g_fixA_c1[li], c2 = g_fixA_c2[li];
        int img = r >> 10, hw = r & 1023;
        const float* zp = Z + (size_t)img * (CDIM * HW) + hw;
        const float* e1 = E + (size_t)c1 * CDIM;
        const float* e2 = E + (size_t)c2 * CDIM;

        float zv[8], p1 = 0.f, p2 = 0.f;
#pragma unroll
        for (int q = 0; q < 8; q++) {
            int k = lane * 8 + q;
            zv[q] = zp[(size_t)k * HW];
            p1 = fmaf(zv[q], e1[k], p1);
            p2 = fmaf(zv[q], e2[k], p2);
        }
#pragma unroll
        for (int o = 16; o > 0; o >>= 1) {
            p1 += __shfl_xor_sync(0xffffffffu, p1, o);
            p2 += __shfl_xor_sync(0xffffffffu, p2, o);
        }
        int win = 0;
        if (lane == 0) {
            float nz = g_nz[r];
            float d1 = fmaf(-2.0f, p1, nz) + g_ne[c1];
            float d2 = fmaf(-2.0f, p2, nz) + g_ne[c2];
            win = (d2 < d1 || (d2 == d1 && c2 < c1)) ? c2 : c1;
        }
        win = __shfl_sync(0xffffffffu, win, 0);
        if (win != c1) {
            const float* en = E + (size_t)win * CDIM;
            float delta = 0.f;
#pragma unroll
            for (int q = 0; q < 8; q++) {
                int k = lane * 8 + q;
                float a = en[k], bo = e1[k];
                out[(size_t)img * (CDIM * HW) + (size_t)k * HW + hw] = a;
                float dn = zv[q] - a, dl = zv[q] - bo;
                delta += dn * dn - dl * dl;
            }
#pragma unroll
            for (int o = 16; o > 0; o >>= 1)
                delta += __shfl_xor_sync(0xffffffffu, delta, o);
            if (lane == 0) {
                atomicAdd(&g_loss, (double)delta);
                g_code[r] = win;
            }
        }
    }
}

// ======== fix B: full 1024-code exact rescan, one block per rare row ========
__global__ void __launch_bounds__(256, 1)
vq_fixB(const float* __restrict__ Z, const float* __restrict__ E,
        float* __restrict__ out) {
    __shared__ float zs[CDIM];
    __shared__ float sd[256];
    __shared__ int   si[256];
    const int tid = threadIdx.x;
    int nb = g_cntB; if (nb > FIXBCAP) nb = FIXBCAP;

    for (int li = blockIdx.x; li < nb; li += gridDim.x) {
        int r = g_fixB_row[li];
        int img = r >> 10, hw = r & 1023;
        const float* zp = Z + (size_t)img * (CDIM * HW) + hw;
        __syncthreads();
        if (tid < 256) zs[tid] = zp[(size_t)tid * HW];
        __syncthreads();
        float nz = g_nz[r];

        float bd = 3.4e38f; int bi = 0;
#pragma unroll
        for (int q = 0; q < 4; q++) {
            int c = tid * 4 + q;
            const float4* ev = (const float4*)(E + (size_t)c * CDIM);
            const float4* z4 = (const float4*)zs;
            float dot = 0.f;
#pragma unroll 8
            for (int k4 = 0; k4 < 64; k4++) {
                float4 e4 = ev[k4], zq = z4[k4];
                dot = fmaf(zq.x, e4.x, dot);
                dot = fmaf(zq.y, e4.y, dot);
                dot = fmaf(zq.z, e4.z, dot);
                dot = fmaf(zq.w, e4.w, dot);
            }
            float d = fmaf(-2.0f, dot, nz) + g_ne[c];
            if (d < bd) { bd = d; bi = c; }
        }
        sd[tid] = bd; si[tid] = bi;
        __syncthreads();
        for (int st = 128; st > 0; st >>= 1) {
            if (tid < st) {
                float od = sd[tid + st]; int oi = si[tid + st];
                if (od < sd[tid] || (od == sd[tid] && oi < si[tid])) {
                    sd[tid] = od; si[tid] = oi;
                }
            }
            __syncthreads();
        }
        int w = si[0], oc = g_code[r];
        __syncthreads();
        if (w != oc) {
            const float* en = E + (size_t)w * CDIM;
            const float* eo = E + (size_t)oc * CDIM;
            float delta = 0.f;
            if (tid < 256) {
                float a = en[tid], bo = eo[tid];
                float zvv = zs[tid];
                out[(size_t)img * (CDIM * HW) + (size_t)tid * HW + hw] = a;
                float dn = zvv - a, dl = zvv - bo;
                delta = dn * dn - dl * dl;
            }
            for (int o = 16; o > 0; o >>= 1)
                delta += __shfl_xor_sync(0xffffffffu, delta, o);
            __syncthreads();
            if ((tid & 31) == 0) sd[tid >> 5] = delta;
            __syncthreads();
            if (tid == 0) {
                float t = 0.f;
                for (int ww = 0; ww < 8; ww++) t += sd[ww];
                atomicAdd(&g_loss, (double)t);
                g_code[r] = w;
            }
        }
        __syncthreads();
    }
}

// ======== finalize scalars ========
__global__ void vq_final(float* out, int out_size) {
    if (out_size >= QELEMS + 1) {
        float vq = (float)(g_loss / (double)QELEMS);
        out[QELEMS] = vq;
        if (out_size >= QELEMS + 2) out[QELEMS + 1] = 0.25f * vq;
    }
}

extern "C" void kernel_launch(void* const* d_in, const int* in_sizes, int n_in,
                              void* d_out, int out_size) {
    const float* Z = (const float*)d_in[0];
    const float* E = (const float*)d_in[1];
    if (n_in >= 2 && in_sizes[0] == KCODES * CDIM && in_sizes[1] == QELEMS) {
        const float* t = Z; Z = E; E = t;
    }
    float* out = (float*)d_out;

    cudaFuncSetAttribute(vq_main, cudaFuncAttributeMaxDynamicSharedMemorySize, SMEM_TOTAL);
    vq_prep_e<<<KCODES, 64>>>(E);
    vq_prep_nz<<<NVEC / 128, 128>>>(Z);
    vq_main<<<NVEC / 128, 256, SMEM_TOTAL>>>(Z, E, out);
    vq_fixA<<<256, 128>>>(Z, E, out);
    vq_fixB<<<64, 256>>>(Z, E, out);
    vq_final<<<1, 1>>>(out, out_size);
}